// round 1
// baseline (speedup 1.0000x reference)
#include <cuda_runtime.h>
#include <cuda_bf16.h>
#include <mma.h>

using namespace nvcuda;

#define NB 32768
#define NC 1024
#define NCH 256
#define NR 16

// ---------------- device scratch (static, no runtime allocation) ----------------
__device__ __nv_bfloat16 g_hn[(size_t)NB * NC];     // LN output, bf16
__device__ __nv_bfloat16 g_h1[(size_t)NB * NCH];    // GLU output
__device__ __nv_bfloat16 g_u [(size_t)NB * NCH];    // GELU output
__device__ __nv_bfloat16 g_Wcat[NC * 2 * NCH];      // [Wd*dw_w | Wg] bf16, [1024,512]
__device__ __nv_bfloat16 g_W1b[NCH * NCH];
__device__ __nv_bfloat16 g_Wbig[NCH * NC];
__device__ float g_T1[NCH * NR];
__device__ float g_Wueff[NCH * NC];
__device__ float g_Wf1[NCH * NCH];
__device__ float g_Wf2[NCH * NCH];
__device__ float g_Wbigf[NCH * NC];
__device__ float g_v1[NCH];
__device__ float g_v2[NCH];
__device__ float g_bu1[NR];
__device__ float g_bueff[NC];
__device__ float g_bbig[NC];

// ---------------- precompute kernels (weight folding) ----------------

// T1 = Wu @ Wld   [256,16], K=1024
__global__ void k_T1(const float* __restrict__ Wu, const float* __restrict__ Wld) {
    int gid = blockIdx.x * blockDim.x + threadIdx.x;   // 0..4095
    int i = gid >> 4, r = gid & 15;
    float s = 0.f;
    for (int c = 0; c < NC; c++) s += Wu[i * NC + c] * Wld[c * NR + r];
    g_T1[i * NR + r] = s;
}

// bu1 = bu @ Wld  [16]
__global__ void k_bu1(const float* __restrict__ bu, const float* __restrict__ Wld) {
    int r = threadIdx.x;
    float s = 0.f;
    for (int c = 0; c < NC; c++) s += bu[c] * Wld[c * NR + r];
    g_bu1[r] = s;
}

// Wu_eff = Wu + T1 @ Wlu   [256,1024]
__global__ void k_Wueff(const float* __restrict__ Wu, const float* __restrict__ Wlu) {
    int idx = blockIdx.x * 256 + threadIdx.x;
    int i = idx >> 10, c = idx & 1023;
    float s = Wu[idx];
    #pragma unroll
    for (int r = 0; r < NR; r++) s += g_T1[i * NR + r] * Wlu[r * NC + c];
    g_Wueff[idx] = s;
}

// bu_eff = bu + bu1 @ Wlu  [1024]
__global__ void k_bueff(const float* __restrict__ bu, const float* __restrict__ Wlu) {
    int c = blockIdx.x * 256 + threadIdx.x;
    float s = bu[c];
    #pragma unroll
    for (int r = 0; r < NR; r++) s += g_bu1[r] * Wlu[r * NC + c];
    g_bueff[c] = s;
}

// generic fp32 GEMM C = A@B (row-major), selector picks operands/dest from globals.
// which: 0 -> g_Wf1 = Aext@Bext ; 1 -> g_Wf2 = g_Wf1@Bext ; 2 -> g_Wbigf = g_Wf2@g_Wueff
__global__ void gemm_f32(int which, const float* __restrict__ Aext,
                         const float* __restrict__ Bext, int M, int N, int K) {
    const float* A; const float* B; float* C;
    if (which == 0)      { A = Aext;   B = Bext;    C = g_Wf1;  }
    else if (which == 1) { A = g_Wf1;  B = Bext;    C = g_Wf2;  }
    else                 { A = g_Wf2;  B = g_Wueff; C = g_Wbigf;}

    __shared__ float As[64][17];
    __shared__ float Bs[16][64];
    int m0 = blockIdx.y * 64, n0 = blockIdx.x * 64;
    int tid = threadIdx.x;
    int ty = tid >> 4, tx = tid & 15;
    float acc[4][4] = {};
    for (int k0 = 0; k0 < K; k0 += 16) {
        #pragma unroll
        for (int l = 0; l < 4; l++) {
            int idx = tid + l * 256;
            int r = idx >> 4, c = idx & 15;
            As[r][c] = A[(size_t)(m0 + r) * K + k0 + c];
        }
        #pragma unroll
        for (int l = 0; l < 4; l++) {
            int idx = tid + l * 256;
            int r = idx >> 6, c = idx & 63;
            Bs[r][c] = B[(size_t)(k0 + r) * N + n0 + c];
        }
        __syncthreads();
        #pragma unroll
        for (int k = 0; k < 16; k++) {
            float a[4], b[4];
            #pragma unroll
            for (int i = 0; i < 4; i++) a[i] = As[ty * 4 + i][k];
            #pragma unroll
            for (int j = 0; j < 4; j++) b[j] = Bs[k][tx * 4 + j];
            #pragma unroll
            for (int i = 0; i < 4; i++)
                #pragma unroll
                for (int j = 0; j < 4; j++) acc[i][j] += a[i] * b[j];
        }
        __syncthreads();
    }
    #pragma unroll
    for (int i = 0; i < 4; i++)
        #pragma unroll
        for (int j = 0; j < 4; j++)
            C[(size_t)(m0 + ty * 4 + i) * N + n0 + tx * 4 + j] = acc[i][j];
}

// v1 = b2@Wv + bv
__global__ void k_v1(const float* __restrict__ b2, const float* __restrict__ Wv,
                     const float* __restrict__ bv) {
    int n = threadIdx.x;
    float s = bv[n];
    for (int k = 0; k < NCH; k++) s += b2[k] * Wv[k * NCH + n];
    g_v1[n] = s;
}
// v2 = v1@Wo + bo
__global__ void k_v2(const float* __restrict__ Wo, const float* __restrict__ bo) {
    int n = threadIdx.x;
    float s = bo[n];
    for (int k = 0; k < NCH; k++) s += g_v1[k] * Wo[k * NCH + n];
    g_v2[n] = s;
}
// b_big = v2@Wu_eff + bu_eff
__global__ void k_bbig() {
    int n = blockIdx.x * 256 + threadIdx.x;
    float s = g_bueff[n];
    for (int k = 0; k < NCH; k++) s += g_v2[k] * g_Wueff[k * NC + n];
    g_bbig[n] = s;
}

// bf16 conversions
__global__ void k_convWcat(const float* __restrict__ Wd, const float* __restrict__ dww,
                           const float* __restrict__ Wg) {
    int idx = blockIdx.x * 256 + threadIdx.x;   // < 1024*512
    int k = idx >> 9, j = idx & 511;
    float v = (j < NCH) ? Wd[k * NCH + j] * dww[j] : Wg[k * NCH + (j - NCH)];
    g_Wcat[idx] = __float2bfloat16(v);
}
__global__ void k_convW1(const float* __restrict__ W1) {
    int idx = blockIdx.x * 256 + threadIdx.x;
    g_W1b[idx] = __float2bfloat16(W1[idx]);
}
__global__ void k_convWbig() {
    int idx = blockIdx.x * 256 + threadIdx.x;
    g_Wbig[idx] = __float2bfloat16(g_Wbigf[idx]);
}

// ---------------- LayerNorm: x[B,1024] -> g_hn bf16 ----------------
__global__ void k_ln(const float* __restrict__ x, const float* __restrict__ lg,
                     const float* __restrict__ lb) {
    int row = blockIdx.x, tid = threadIdx.x;
    float4 v = ((const float4*)(x + (size_t)row * NC))[tid];
    float s = v.x + v.y + v.z + v.w;
    float q = fmaf(v.x, v.x, fmaf(v.y, v.y, fmaf(v.z, v.z, v.w * v.w)));
    #pragma unroll
    for (int o = 16; o > 0; o >>= 1) {
        s += __shfl_xor_sync(0xffffffffu, s, o);
        q += __shfl_xor_sync(0xffffffffu, q, o);
    }
    __shared__ float sS[8], sQ[8];
    int wid = tid >> 5, lane = tid & 31;
    if (lane == 0) { sS[wid] = s; sQ[wid] = q; }
    __syncthreads();
    if (tid == 0) {
        float S = 0.f, Q = 0.f;
        #pragma unroll
        for (int i = 0; i < 8; i++) { S += sS[i]; Q += sQ[i]; }
        sS[0] = S; sQ[0] = Q;
    }
    __syncthreads();
    float mean = sS[0] * (1.f / NC);
    float var  = sQ[0] * (1.f / NC) - mean * mean;
    float rstd = rsqrtf(var + 1e-5f);
    float4 g4 = ((const float4*)lg)[tid];
    float4 b4 = ((const float4*)lb)[tid];
    __align__(8) __nv_bfloat16 o4[4];
    o4[0] = __float2bfloat16((v.x - mean) * rstd * g4.x + b4.x);
    o4[1] = __float2bfloat16((v.y - mean) * rstd * g4.y + b4.y);
    o4[2] = __float2bfloat16((v.z - mean) * rstd * g4.z + b4.z);
    o4[3] = __float2bfloat16((v.w - mean) * rstd * g4.w + b4.w);
    *(uint2*)(g_hn + (size_t)row * NC + tid * 4) = *(const uint2*)o4;
}

// ---------------- main wmma GEMM kernels ----------------
__device__ __forceinline__ float gelu_tanh(float v) {
    return 0.5f * v * (1.f + tanhf(0.7978845608028654f * (v + 0.044715f * v * v * v)));
}

// GLU GEMM: [B,1024] @ [1024, 2x256] -> glu epilogue -> g_h1 bf16
// CTA: 128 rows x 64 cols of CH, dual accumulators (a-half / g-half of Wcat).
__global__ void k_gemm_glu(const float* __restrict__ bd, const float* __restrict__ dww,
                           const float* __restrict__ bg, const float* __restrict__ dwb) {
    extern __shared__ char smem[];
    __nv_bfloat16* As  = (__nv_bfloat16*)smem;              // 128x48  = 12288 B
    __nv_bfloat16* BsA = (__nv_bfloat16*)(smem + 12288);    // 32x80   =  5120 B
    __nv_bfloat16* BsG = (__nv_bfloat16*)(smem + 17408);    // 32x80
    float* Ep = (float*)smem;                               // epilogue reuse (8x32x32 f32)

    const int tid = threadIdx.x, wid = tid >> 5, lane = tid & 31;
    const int wm = wid >> 1, wn = wid & 1;
    const int m0 = blockIdx.y * 128;
    const int n0 = blockIdx.x * 64;

    wmma::fragment<wmma::accumulator, 16, 16, 16, float> accA[2][2], accG[2][2];
    #pragma unroll
    for (int i = 0; i < 2; i++)
        #pragma unroll
        for (int j = 0; j < 2; j++) {
            wmma::fill_fragment(accA[i][j], 0.f);
            wmma::fill_fragment(accG[i][j], 0.f);
        }

    const int ar = tid >> 2, ac = (tid & 3) << 3;
    const int ar2 = (tid + 256) >> 2, ac2 = ((tid + 256) & 3) << 3;
    const int br = tid >> 3, bc = (tid & 7) << 3;

    for (int k0 = 0; k0 < NC; k0 += 32) {
        *(uint4*)(As + ar  * 48 + ac ) = *(const uint4*)(g_hn + (size_t)(m0 + ar ) * NC + k0 + ac );
        *(uint4*)(As + ar2 * 48 + ac2) = *(const uint4*)(g_hn + (size_t)(m0 + ar2) * NC + k0 + ac2);
        *(uint4*)(BsA + br * 80 + bc)  = *(const uint4*)(g_Wcat + (size_t)(k0 + br) * 512 + n0 + bc);
        *(uint4*)(BsG + br * 80 + bc)  = *(const uint4*)(g_Wcat + (size_t)(k0 + br) * 512 + 256 + n0 + bc);
        __syncthreads();
        #pragma unroll
        for (int kk = 0; kk < 32; kk += 16) {
            wmma::fragment<wmma::matrix_a, 16, 16, 16, __nv_bfloat16, wmma::row_major> af[2];
            wmma::fragment<wmma::matrix_b, 16, 16, 16, __nv_bfloat16, wmma::row_major> bA[2], bG[2];
            #pragma unroll
            for (int i = 0; i < 2; i++)
                wmma::load_matrix_sync(af[i], As + (wm * 32 + i * 16) * 48 + kk, 48);
            #pragma unroll
            for (int j = 0; j < 2; j++) {
                wmma::load_matrix_sync(bA[j], BsA + kk * 80 + wn * 32 + j * 16, 80);
                wmma::load_matrix_sync(bG[j], BsG + kk * 80 + wn * 32 + j * 16, 80);
            }
            #pragma unroll
            for (int i = 0; i < 2; i++)
                #pragma unroll
                for (int j = 0; j < 2; j++) {
                    wmma::mma_sync(accA[i][j], af[i], bA[j], accA[i][j]);
                    wmma::mma_sync(accG[i][j], af[i], bG[j], accG[i][j]);
                }
        }
        __syncthreads();
    }

    float* patch = Ep + wid * 1024;
    #pragma unroll
    for (int i = 0; i < 2; i++)
        #pragma unroll
        for (int j = 0; j < 2; j++)
            wmma::store_matrix_sync(patch + i * 16 * 32 + j * 16, accA[i][j], 32, wmma::mem_row_major);
    __syncwarp();
    float av[32];
    #pragma unroll
    for (int c = 0; c < 32; c++) av[c] = patch[lane * 32 + c];
    __syncwarp();
    #pragma unroll
    for (int i = 0; i < 2; i++)
        #pragma unroll
        for (int j = 0; j < 2; j++)
            wmma::store_matrix_sync(patch + i * 16 * 32 + j * 16, accG[i][j], 32, wmma::mem_row_major);
    __syncwarp();

    const int gr = m0 + wm * 32 + lane;
    const int gc0 = n0 + wn * 32;
    #pragma unroll
    for (int c8 = 0; c8 < 32; c8 += 8) {
        __align__(16) __nv_bfloat16 tmp[8];
        #pragma unroll
        for (int t = 0; t < 8; t++) {
            int j = gc0 + c8 + t;
            float a = av[c8 + t] + bd[j] * dww[j];
            float g = patch[lane * 32 + c8 + t] + bg[j];
            float sg = 1.f / (1.f + expf(-g));
            tmp[t] = __float2bfloat16(a * sg + dwb[j]);
        }
        *(uint4*)(g_h1 + (size_t)gr * NCH + gc0 + c8) = *(const uint4*)tmp;
    }
}

// MODE 0: g_u = gelu(g_h1 @ g_W1b + b1)           (N=256)
// MODE 1: out = 0.5*(g_u @ g_Wbig + g_bbig) + 0.5*x  (N=1024, fp32 out)
template <int MODE>
__global__ void k_gemm_single(const float* __restrict__ bias, const float* __restrict__ x,
                              float* __restrict__ out) {
    constexpr int NN = (MODE == 0) ? NCH : NC;
    extern __shared__ char smem[];
    __nv_bfloat16* As = (__nv_bfloat16*)smem;            // 128x48
    __nv_bfloat16* Bs = (__nv_bfloat16*)(smem + 12288);  // 32x80
    float* Ep = (float*)smem;

    const __nv_bfloat16* A = (MODE == 0) ? g_h1 : g_u;
    const __nv_bfloat16* W = (MODE == 0) ? g_W1b : g_Wbig;
    const float* bvec = (MODE == 0) ? bias : g_bbig;

    const int tid = threadIdx.x, wid = tid >> 5, lane = tid & 31;
    const int wm = wid >> 1, wn = wid & 1;
    const int m0 = blockIdx.y * 128;
    const int n0 = blockIdx.x * 64;

    wmma::fragment<wmma::accumulator, 16, 16, 16, float> acc[2][2];
    #pragma unroll
    for (int i = 0; i < 2; i++)
        #pragma unroll
        for (int j = 0; j < 2; j++) wmma::fill_fragment(acc[i][j], 0.f);

    const int ar = tid >> 2, ac = (tid & 3) << 3;
    const int ar2 = (tid + 256) >> 2, ac2 = ((tid + 256) & 3) << 3;
    const int br = tid >> 3, bc = (tid & 7) << 3;

    for (int k0 = 0; k0 < NCH; k0 += 32) {
        *(uint4*)(As + ar  * 48 + ac ) = *(const uint4*)(A + (size_t)(m0 + ar ) * NCH + k0 + ac );
        *(uint4*)(As + ar2 * 48 + ac2) = *(const uint4*)(A + (size_t)(m0 + ar2) * NCH + k0 + ac2);
        *(uint4*)(Bs + br * 80 + bc)   = *(const uint4*)(W + (size_t)(k0 + br) * NN + n0 + bc);
        __syncthreads();
        #pragma unroll
        for (int kk = 0; kk < 32; kk += 16) {
            wmma::fragment<wmma::matrix_a, 16, 16, 16, __nv_bfloat16, wmma::row_major> af[2];
            wmma::fragment<wmma::matrix_b, 16, 16, 16, __nv_bfloat16, wmma::row_major> bf[2];
            #pragma unroll
            for (int i = 0; i < 2; i++)
                wmma::load_matrix_sync(af[i], As + (wm * 32 + i * 16) * 48 + kk, 48);
            #pragma unroll
            for (int j = 0; j < 2; j++)
                wmma::load_matrix_sync(bf[j], Bs + kk * 80 + wn * 32 + j * 16, 80);
            #pragma unroll
            for (int i = 0; i < 2; i++)
                #pragma unroll
                for (int j = 0; j < 2; j++)
                    wmma::mma_sync(acc[i][j], af[i], bf[j], acc[i][j]);
        }
        __syncthreads();
    }

    float* patch = Ep + wid * 1024;
    #pragma unroll
    for (int i = 0; i < 2; i++)
        #pragma unroll
        for (int j = 0; j < 2; j++)
            wmma::store_matrix_sync(patch + i * 16 * 32 + j * 16, acc[i][j], 32, wmma::mem_row_major);
    __syncwarp();

    const int gr = m0 + wm * 32 + lane;
    const int gc0 = n0 + wn * 32;
    if (MODE == 0) {
        #pragma unroll
        for (int c8 = 0; c8 < 32; c8 += 8) {
            __align__(16) __nv_bfloat16 tmp[8];
            #pragma unroll
            for (int t = 0; t < 8; t++) {
                int j = gc0 + c8 + t;
                float v = patch[lane * 32 + c8 + t] + bvec[j];
                tmp[t] = __float2bfloat16(gelu_tanh(v));
            }
            *(uint4*)(g_u + (size_t)gr * NCH + gc0 + c8) = *(const uint4*)tmp;
        }
    } else {
        #pragma unroll
        for (int c4 = 0; c4 < 32; c4 += 4) {
            float4 xo = *(const float4*)(x + (size_t)gr * NC + gc0 + c4);
            float4 r;
            r.x = 0.5f * (patch[lane * 32 + c4 + 0] + bvec[gc0 + c4 + 0]) + 0.5f * xo.x;
            r.y = 0.5f * (patch[lane * 32 + c4 + 1] + bvec[gc0 + c4 + 1]) + 0.5f * xo.y;
            r.z = 0.5f * (patch[lane * 32 + c4 + 2] + bvec[gc0 + c4 + 2]) + 0.5f * xo.z;
            r.w = 0.5f * (patch[lane * 32 + c4 + 3] + bvec[gc0 + c4 + 3]) + 0.5f * xo.w;
            *(float4*)(out + (size_t)gr * NC + gc0 + c4) = r;
        }
    }
}

// ---------------- host launch ----------------
extern "C" void kernel_launch(void* const* d_in, const int* in_sizes, int n_in,
                              void* d_out, int out_size) {
    const float* x   = (const float*)d_in[0];
    const float* lng = (const float*)d_in[1];
    const float* lnb = (const float*)d_in[2];
    const float* Wd  = (const float*)d_in[3];
    const float* bd  = (const float*)d_in[4];
    const float* Wg  = (const float*)d_in[5];
    const float* bg  = (const float*)d_in[6];
    const float* dww = (const float*)d_in[7];
    const float* dwb = (const float*)d_in[8];
    const float* W1  = (const float*)d_in[9];
    const float* b1  = (const float*)d_in[10];
    const float* W2  = (const float*)d_in[11];
    const float* b2  = (const float*)d_in[12];
    // d_in[13..16] = Wq,bq,Wk,bk — dead code (softmax over 1 key == 1)
    const float* Wv  = (const float*)d_in[17];
    const float* bv  = (const float*)d_in[18];
    const float* Wo  = (const float*)d_in[19];
    const float* bo  = (const float*)d_in[20];
    const float* Wu  = (const float*)d_in[21];
    const float* bu  = (const float*)d_in[22];
    const float* Wld = (const float*)d_in[23];
    const float* Wlu = (const float*)d_in[24];
    float* out = (float*)d_out;

    // ---- weight folding (one-time per launch, ~0.2 GFLOP) ----
    k_T1<<<16, 256>>>(Wu, Wld);
    k_bu1<<<1, 16>>>(bu, Wld);
    k_Wueff<<<1024, 256>>>(Wu, Wlu);
    k_bueff<<<4, 256>>>(bu, Wlu);
    gemm_f32<<<dim3(4, 4), 256>>>(0, W2, Wv, NCH, NCH, NCH);       // Wf1 = W2@Wv
    gemm_f32<<<dim3(4, 4), 256>>>(1, nullptr, Wo, NCH, NCH, NCH);  // Wf2 = Wf1@Wo
    gemm_f32<<<dim3(16, 4), 256>>>(2, nullptr, nullptr, NCH, NC, NCH); // Wbigf = Wf2@Wueff
    k_v1<<<1, 256>>>(b2, Wv, bv);
    k_v2<<<1, 256>>>(Wo, bo);
    k_bbig<<<4, 256>>>();
    k_convWcat<<<2048, 256>>>(Wd, dww, Wg);
    k_convW1<<<256, 256>>>(W1);
    k_convWbig<<<1024, 256>>>();

    // ---- main pipeline ----
    k_ln<<<NB, 256>>>(x, lng, lnb);
    k_gemm_glu<<<dim3(4, 256), 256, 32768>>>(bd, dww, bg, dwb);
    k_gemm_single<0><<<dim3(4, 256), 256, 32768>>>(b1, nullptr, nullptr);
    k_gemm_single<1><<<dim3(16, 256), 256, 32768>>>(nullptr, x, out);
}

// round 4
// speedup vs baseline: 1.1007x; 1.1007x over previous
#include <cuda_runtime.h>
#include <cuda_bf16.h>
#include <mma.h>
#include <cstdint>

using namespace nvcuda;

#define NB 32768
#define NC 1024
#define NCH 256
#define NR 16

// ---------------- device scratch ----------------
__device__ __nv_bfloat16 g_h1[(size_t)NB * NCH];    // GLU output
__device__ __nv_bfloat16 g_Wcat[NC * 2 * NCH];      // [Wd*dw_w | Wg] bf16, [1024,512]
__device__ __nv_bfloat16 g_W1b[NCH * NCH];
__device__ __nv_bfloat16 g_Wbig[NCH * NC];
__device__ float g_T1[NCH * NR];
__device__ float g_Wueff[NCH * NC];
__device__ float g_Wf1[NCH * NCH];
__device__ float g_Wf2[NCH * NCH];
__device__ float g_Wbigf[NCH * NC];
__device__ float g_v1[NCH];
__device__ float g_v2[NCH];
__device__ float g_bu1[NR];
__device__ float g_bueff[NC];
__device__ float g_bbig[NC];

// ---------------- cp.async helpers ----------------
__device__ __forceinline__ void cp16(void* s, const void* g) {
    unsigned int sa = (unsigned int)__cvta_generic_to_shared(s);
    asm volatile("cp.async.cg.shared.global [%0], [%1], 16;\n" :: "r"(sa), "l"(g));
}
__device__ __forceinline__ void cp_commit() { asm volatile("cp.async.commit_group;\n" ::: "memory"); }
template<int N>
__device__ __forceinline__ void cp_wait() { asm volatile("cp.async.wait_group %0;\n" :: "n"(N) : "memory"); }

// ---------------- precompute (weight folding) ----------------

__global__ void k_T1(const float* __restrict__ Wu, const float* __restrict__ Wld) {
    int i = blockIdx.x;
    int tid = threadIdx.x, wid = tid >> 5, lane = tid & 31;
    float acc[NR];
    #pragma unroll
    for (int r = 0; r < NR; r++) acc[r] = 0.f;
    for (int c = tid; c < NC; c += 256) {
        float w = Wu[i * NC + c];
        #pragma unroll
        for (int r = 0; r < NR; r++) acc[r] += w * Wld[c * NR + r];
    }
    #pragma unroll
    for (int r = 0; r < NR; r++)
        #pragma unroll
        for (int o = 16; o > 0; o >>= 1) acc[r] += __shfl_xor_sync(0xffffffffu, acc[r], o);
    __shared__ float s[8][NR];
    if (lane == 0)
        #pragma unroll
        for (int r = 0; r < NR; r++) s[wid][r] = acc[r];
    __syncthreads();
    if (tid < NR) {
        float v = 0.f;
        #pragma unroll
        for (int w = 0; w < 8; w++) v += s[w][tid];
        g_T1[i * NR + tid] = v;
    }
}

__global__ void k_bu1(const float* __restrict__ bu, const float* __restrict__ Wld) {
    int r = threadIdx.x;
    float s = 0.f;
    for (int c = 0; c < NC; c++) s += bu[c] * Wld[c * NR + r];
    g_bu1[r] = s;
}

__global__ void k_Wueff(const float* __restrict__ Wu, const float* __restrict__ Wlu) {
    int idx = blockIdx.x * 256 + threadIdx.x;
    int i = idx >> 10, c = idx & 1023;
    float s = Wu[idx];
    #pragma unroll
    for (int r = 0; r < NR; r++) s += g_T1[i * NR + r] * Wlu[r * NC + c];
    g_Wueff[idx] = s;
}

__global__ void k_bueff(const float* __restrict__ bu, const float* __restrict__ Wlu) {
    int c = blockIdx.x * 256 + threadIdx.x;
    float s = bu[c];
    #pragma unroll
    for (int r = 0; r < NR; r++) s += g_bu1[r] * Wlu[r * NC + c];
    g_bueff[c] = s;
}

__global__ void gemm_f32(int which, const float* __restrict__ Aext,
                         const float* __restrict__ Bext, int M, int N, int K) {
    const float* A; const float* B; float* C;
    if (which == 0)      { A = Aext;   B = Bext;    C = g_Wf1;  }
    else if (which == 1) { A = g_Wf1;  B = Bext;    C = g_Wf2;  }
    else                 { A = g_Wf2;  B = g_Wueff; C = g_Wbigf;}

    __shared__ float As[64][17];
    __shared__ float Bs[16][64];
    int m0 = blockIdx.y * 64, n0 = blockIdx.x * 64;
    int tid = threadIdx.x;
    int ty = tid >> 4, tx = tid & 15;
    float acc[4][4] = {};
    for (int k0 = 0; k0 < K; k0 += 16) {
        #pragma unroll
        for (int l = 0; l < 4; l++) {
            int idx = tid + l * 256;
            int r = idx >> 4, c = idx & 15;
            As[r][c] = A[(size_t)(m0 + r) * K + k0 + c];
        }
        #pragma unroll
        for (int l = 0; l < 4; l++) {
            int idx = tid + l * 256;
            int r = idx >> 6, c = idx & 63;
            Bs[r][c] = B[(size_t)(k0 + r) * N + n0 + c];
        }
        __syncthreads();
        #pragma unroll
        for (int k = 0; k < 16; k++) {
            float a[4], b[4];
            #pragma unroll
            for (int i = 0; i < 4; i++) a[i] = As[ty * 4 + i][k];
            #pragma unroll
            for (int j = 0; j < 4; j++) b[j] = Bs[k][tx * 4 + j];
            #pragma unroll
            for (int i = 0; i < 4; i++)
                #pragma unroll
                for (int j = 0; j < 4; j++) acc[i][j] += a[i] * b[j];
        }
        __syncthreads();
    }
    #pragma unroll
    for (int i = 0; i < 4; i++)
        #pragma unroll
        for (int j = 0; j < 4; j++)
            C[(size_t)(m0 + ty * 4 + i) * N + n0 + tx * 4 + j] = acc[i][j];
}

__global__ void k_v1(const float* __restrict__ b2, const float* __restrict__ Wv,
                     const float* __restrict__ bv) {
    int n = threadIdx.x;
    float s = bv[n];
    for (int k = 0; k < NCH; k++) s += b2[k] * Wv[k * NCH + n];
    g_v1[n] = s;
}
__global__ void k_v2(const float* __restrict__ Wo, const float* __restrict__ bo) {
    int n = threadIdx.x;
    float s = bo[n];
    for (int k = 0; k < NCH; k++) s += g_v1[k] * Wo[k * NCH + n];
    g_v2[n] = s;
}
__global__ void k_bbig() {
    int n = blockIdx.x * 256 + threadIdx.x;
    float s = g_bueff[n];
    for (int k = 0; k < NCH; k++) s += g_v2[k] * g_Wueff[k * NC + n];
    g_bbig[n] = s;
}

__global__ void k_convWcat(const float* __restrict__ Wd, const float* __restrict__ dww,
                           const float* __restrict__ Wg) {
    int idx = blockIdx.x * 256 + threadIdx.x;
    int k = idx >> 9, j = idx & 511;
    float v = (j < NCH) ? Wd[k * NCH + j] * dww[j] : Wg[k * NCH + (j - NCH)];
    g_Wcat[idx] = __float2bfloat16(v);
}
__global__ void k_convW1(const float* __restrict__ W1) {
    int idx = blockIdx.x * 256 + threadIdx.x;
    g_W1b[idx] = __float2bfloat16(W1[idx]);
}
__global__ void k_convWbig() {
    int idx = blockIdx.x * 256 + threadIdx.x;
    g_Wbig[idx] = __float2bfloat16(g_Wbigf[idx]);
}

// ---------------- fused LN + GLU GEMM ----------------
#define GLU_SAS 1048           // sA stride (bf16 elems)
#define GLU_SBS 520            // sB stride
#define GLU_PS  520            // f32 patch stride
#define GLU_SMEM (64 * GLU_SAS * 2 + 2 * 32 * GLU_SBS * 2)   // 200704

__device__ __forceinline__ void glu_prefB(__nv_bfloat16* sB, int k0, int tid) {
    #pragma unroll
    for (int j = 0; j < 8; j++) {
        int idx = tid + j * 256;
        int row = idx >> 6, c16 = idx & 63;         // 32 rows x 64 chunks = 512 cols
        cp16(sB + row * GLU_SBS + c16 * 8, g_Wcat + (size_t)(k0 + row) * 512 + c16 * 8);
    }
}

__global__ __launch_bounds__(256, 1)
void k_glu(const float* __restrict__ x, const float* __restrict__ lg,
           const float* __restrict__ lb, const float* __restrict__ bd,
           const float* __restrict__ dww, const float* __restrict__ bg,
           const float* __restrict__ dwb) {
    extern __shared__ char smem[];
    __nv_bfloat16* sA  = (__nv_bfloat16*)smem;                      // 64 x 1048
    __nv_bfloat16* sB0 = (__nv_bfloat16*)(smem + 64 * GLU_SAS * 2); // 32 x 520
    __nv_bfloat16* sB1 = sB0 + 32 * GLU_SBS;
    float* patch = (float*)smem;                                    // aliases sA (post-loop)

    const int tid = threadIdx.x, wid = tid >> 5, lane = tid & 31;
    const int m0 = blockIdx.x * 64;

    glu_prefB(sB0, 0, tid);
    cp_commit();

    // ---- LayerNorm: 8 rows per warp -> normalized bf16 in sA ----
    {
        float4 lg4[8], lb4[8];
        #pragma unroll
        for (int i = 0; i < 8; i++) {
            lg4[i] = ((const float4*)lg)[lane + i * 32];
            lb4[i] = ((const float4*)lb)[lane + i * 32];
        }
        #pragma unroll
        for (int rr = 0; rr < 8; rr++) {
            int r = wid * 8 + rr;
            const float4* xr = (const float4*)(x + (size_t)(m0 + r) * NC);
            float4 v[8];
            float s = 0.f, q = 0.f;
            #pragma unroll
            for (int i = 0; i < 8; i++) {
                v[i] = xr[lane + i * 32];
                s += v[i].x + v[i].y + v[i].z + v[i].w;
                q = fmaf(v[i].x, v[i].x, q); q = fmaf(v[i].y, v[i].y, q);
                q = fmaf(v[i].z, v[i].z, q); q = fmaf(v[i].w, v[i].w, q);
            }
            #pragma unroll
            for (int o = 16; o > 0; o >>= 1) {
                s += __shfl_xor_sync(0xffffffffu, s, o);
                q += __shfl_xor_sync(0xffffffffu, q, o);
            }
            float mean = s * (1.f / NC);
            float rstd = rsqrtf(q * (1.f / NC) - mean * mean + 1e-5f);
            #pragma unroll
            for (int i = 0; i < 8; i++) {
                __align__(8) __nv_bfloat16 o4[4];
                o4[0] = __float2bfloat16((v[i].x - mean) * rstd * lg4[i].x + lb4[i].x);
                o4[1] = __float2bfloat16((v[i].y - mean) * rstd * lg4[i].y + lb4[i].y);
                o4[2] = __float2bfloat16((v[i].z - mean) * rstd * lg4[i].z + lb4[i].z);
                o4[3] = __float2bfloat16((v[i].w - mean) * rstd * lg4[i].w + lb4[i].w);
                *(uint2*)(sA + r * GLU_SAS + (lane + i * 32) * 4) = *(const uint2*)o4;
            }
        }
    }
    cp_wait<0>();
    __syncthreads();

    // ---- main K loop ----
    const int wm = wid >> 2, wn = wid & 3;   // warp tile 32x128 of 64x512
    wmma::fragment<wmma::accumulator, 16, 16, 16, float> acc[2][8];
    #pragma unroll
    for (int i = 0; i < 2; i++)
        #pragma unroll
        for (int j = 0; j < 8; j++) wmma::fill_fragment(acc[i][j], 0.f);

    __nv_bfloat16* sBb[2] = { sB0, sB1 };
    for (int k0 = 0; k0 < NC; k0 += 32) {
        int cur = (k0 >> 5) & 1;
        if (k0 + 32 < NC) { glu_prefB(sBb[cur ^ 1], k0 + 32, tid); cp_commit(); }
        #pragma unroll
        for (int kk = 0; kk < 32; kk += 16) {
            wmma::fragment<wmma::matrix_a, 16, 16, 16, __nv_bfloat16, wmma::row_major> af[2];
            wmma::fragment<wmma::matrix_b, 16, 16, 16, __nv_bfloat16, wmma::row_major> bf[8];
            #pragma unroll
            for (int i = 0; i < 2; i++)
                wmma::load_matrix_sync(af[i], sA + (wm * 32 + i * 16) * GLU_SAS + k0 + kk, GLU_SAS);
            #pragma unroll
            for (int j = 0; j < 8; j++)
                wmma::load_matrix_sync(bf[j], sBb[cur] + kk * GLU_SBS + wn * 128 + j * 16, GLU_SBS);
            #pragma unroll
            for (int i = 0; i < 2; i++)
                #pragma unroll
                for (int j = 0; j < 8; j++)
                    wmma::mma_sync(acc[i][j], af[i], bf[j], acc[i][j]);
        }
        cp_wait<0>();
        __syncthreads();
    }

    // ---- epilogue: GLU combine -> g_h1 ----
    #pragma unroll
    for (int i = 0; i < 2; i++)
        #pragma unroll
        for (int j = 0; j < 8; j++)
            wmma::store_matrix_sync(patch + (size_t)(wm * 32 + i * 16) * GLU_PS + wn * 128 + j * 16,
                                    acc[i][j], GLU_PS, wmma::mem_row_major);
    __syncthreads();

    const int r = tid >> 2;
    const int cb = (tid & 3) * 64;
    #pragma unroll
    for (int c8 = 0; c8 < 64; c8 += 8) {
        __align__(16) __nv_bfloat16 tmp[8];
        #pragma unroll
        for (int t = 0; t < 8; t++) {
            int j = cb + c8 + t;
            float a = patch[r * GLU_PS + j] + bd[j] * dww[j];
            float g = patch[r * GLU_PS + 256 + j] + bg[j];
            float sg = 1.f / (1.f + expf(-g));
            tmp[t] = __float2bfloat16(a * sg + dwb[j]);
        }
        *(uint4*)(g_h1 + (size_t)(m0 + r) * NCH + cb + c8) = *(const uint4*)tmp;
    }
}

// ---------------- fused tail ----------------
// smem map (bytes):
//   sA1   [0,      33792)   64 x 264 bf16
//   sW1   [33792, 168960)  256 x 264 bf16
//   patch [33792, 100352)   64 x 260 f32   (aliases sW1 rows 0..~126 — written only
//                                           after GEMM1 k-loop completes)
//   WB0   [101376,135168)   64 x 264 bf16  (aliases sW1 rows >=128 — first prefetch
//                                           issued only after GEMM1 k-loop sync!)
//   WB1   [135168,168960)
//   sU    [168960,202752)   64 x 264 bf16
#define T_S  264
#define T_PS 260
#define T_OFF_A1 0
#define T_OFF_W1 33792
#define T_OFF_PATCH 33792
#define T_OFF_WB0 101376
#define T_OFF_WB1 135168
#define T_OFF_U 168960
#define TAIL_SMEM 202752

__device__ __forceinline__ float gelu_tanh(float v) {
    return 0.5f * v * (1.f + tanhf(0.7978845608028654f * (v + 0.044715f * v * v * v)));
}

__device__ __forceinline__ void tail_prefWb(char* smem, int buf, int ch, int k0, int tid) {
    __nv_bfloat16* dst = (__nv_bfloat16*)(smem + (buf ? T_OFF_WB1 : T_OFF_WB0));
    #pragma unroll
    for (int j = 0; j < 8; j++) {
        int idx = tid + j * 256;
        int row = idx >> 5, c16 = idx & 31;       // 64 rows x 32 chunks = 256 cols
        cp16(dst + row * T_S + c16 * 8, g_Wbig + (size_t)(k0 + row) * NC + ch * NCH + c16 * 8);
    }
}

__global__ __launch_bounds__(256, 1)
void k_tail(const float* __restrict__ b1, const float* __restrict__ x,
            float* __restrict__ out) {
    extern __shared__ char smem[];
    __nv_bfloat16* sA1 = (__nv_bfloat16*)(smem + T_OFF_A1);
    __nv_bfloat16* sW1 = (__nv_bfloat16*)(smem + T_OFF_W1);
    __nv_bfloat16* sU  = (__nv_bfloat16*)(smem + T_OFF_U);
    float* patch = (float*)(smem + T_OFF_PATCH);

    const int tid = threadIdx.x, wid = tid >> 5;
    const int wm = wid >> 2, wn = wid & 3;    // warp tile 32x64 of 64x256
    const int m0 = blockIdx.x * 64;

    // phase 0: load A1 tile (64 x 256 = 2048 chunks) + W1 (256 x 256 = 8192 chunks)
    #pragma unroll
    for (int j = 0; j < 8; j++) {
        int idx = tid + j * 256;
        int row = idx >> 5, c16 = idx & 31;       // FIX: full 256-col coverage
        cp16(sA1 + row * T_S + c16 * 8, g_h1 + (size_t)(m0 + row) * NCH + c16 * 8);
    }
    #pragma unroll
    for (int j = 0; j < 32; j++) {
        int idx = tid + j * 256;
        int row = idx >> 5, c16 = idx & 31;
        cp16(sW1 + row * T_S + c16 * 8, g_W1b + (size_t)row * NCH + c16 * 8);
    }
    cp_commit();
    cp_wait<0>();
    __syncthreads();

    // ---- GEMM1: u = gelu(A1 @ W1 + b1) ----
    {
        wmma::fragment<wmma::accumulator, 16, 16, 16, float> acc1[2][4];
        #pragma unroll
        for (int i = 0; i < 2; i++)
            #pragma unroll
            for (int j = 0; j < 4; j++) wmma::fill_fragment(acc1[i][j], 0.f);
        #pragma unroll
        for (int kk = 0; kk < NCH; kk += 16) {
            wmma::fragment<wmma::matrix_a, 16, 16, 16, __nv_bfloat16, wmma::row_major> af[2];
            wmma::fragment<wmma::matrix_b, 16, 16, 16, __nv_bfloat16, wmma::row_major> bf[4];
            #pragma unroll
            for (int i = 0; i < 2; i++)
                wmma::load_matrix_sync(af[i], sA1 + (wm * 32 + i * 16) * T_S + kk, T_S);
            #pragma unroll
            for (int j = 0; j < 4; j++)
                wmma::load_matrix_sync(bf[j], sW1 + kk * T_S + wn * 64 + j * 16, T_S);
            #pragma unroll
            for (int i = 0; i < 2; i++)
                #pragma unroll
                for (int j = 0; j < 4; j++)
                    wmma::mma_sync(acc1[i][j], af[i], bf[j], acc1[i][j]);
        }
        __syncthreads();   // ALL reads of sW1 complete

        // FIX: first Wbig prefetch only now (WB0 aliases sW1 rows >=128);
        // overlaps the GEMM1 epilogue below.
        tail_prefWb(smem, 0, 0, 0, tid);
        cp_commit();

        #pragma unroll
        for (int i = 0; i < 2; i++)
            #pragma unroll
            for (int j = 0; j < 4; j++)
                wmma::store_matrix_sync(patch + (size_t)(wm * 32 + i * 16) * T_PS + wn * 64 + j * 16,
                                        acc1[i][j], T_PS, wmma::mem_row_major);
        __syncthreads();
        const int r = tid >> 2, cb = (tid & 3) * 64;
        #pragma unroll
        for (int c8 = 0; c8 < 64; c8 += 8) {
            __align__(16) __nv_bfloat16 tmp[8];
            #pragma unroll
            for (int t = 0; t < 8; t++) {
                int j = cb + c8 + t;
                tmp[t] = __float2bfloat16(gelu_tanh(patch[r * T_PS + j] + b1[j]));
            }
            *(uint4*)(sU + r * T_S + cb + c8) = *(const uint4*)tmp;
        }
        __syncthreads();
    }

    // ---- GEMM2: per 256-col chunk, Wbig double-buffered ----
    for (int ch = 0; ch < 4; ch++) {
        wmma::fragment<wmma::accumulator, 16, 16, 16, float> acc2[2][4];
        #pragma unroll
        for (int i = 0; i < 2; i++)
            #pragma unroll
            for (int j = 0; j < 4; j++) wmma::fill_fragment(acc2[i][j], 0.f);

        for (int k0 = 0; k0 < NCH; k0 += 64) {
            int t = ch * 4 + (k0 >> 6);
            int cur = t & 1;
            cp_wait<0>();
            __syncthreads();
            if (k0 + 64 < NCH)       tail_prefWb(smem, cur ^ 1, ch, k0 + 64, tid);
            else if (ch + 1 < 4)     tail_prefWb(smem, cur ^ 1, ch + 1, 0, tid);
            if (t < 15) cp_commit();
            __nv_bfloat16* sWb = (__nv_bfloat16*)(smem + (cur ? T_OFF_WB1 : T_OFF_WB0));
            #pragma unroll
            for (int kk = 0; kk < 64; kk += 16) {
                wmma::fragment<wmma::matrix_a, 16, 16, 16, __nv_bfloat16, wmma::row_major> af[2];
                wmma::fragment<wmma::matrix_b, 16, 16, 16, __nv_bfloat16, wmma::row_major> bf[4];
                #pragma unroll
                for (int i = 0; i < 2; i++)
                    wmma::load_matrix_sync(af[i], sU + (wm * 32 + i * 16) * T_S + k0 + kk, T_S);
                #pragma unroll
                for (int j = 0; j < 4; j++)
                    wmma::load_matrix_sync(bf[j], sWb + kk * T_S + wn * 64 + j * 16, T_S);
                #pragma unroll
                for (int i = 0; i < 2; i++)
                    #pragma unroll
                    for (int j = 0; j < 4; j++)
                        wmma::mma_sync(acc2[i][j], af[i], bf[j], acc2[i][j]);
            }
            __syncthreads();
        }

        #pragma unroll
        for (int i = 0; i < 2; i++)
            #pragma unroll
            for (int j = 0; j < 4; j++)
                wmma::store_matrix_sync(patch + (size_t)(wm * 32 + i * 16) * T_PS + wn * 64 + j * 16,
                                        acc2[i][j], T_PS, wmma::mem_row_major);
        __syncthreads();
        const int r = tid >> 2, cb = (tid & 3) * 64;
        const int gr = m0 + r;
        #pragma unroll
        for (int c4 = 0; c4 < 64; c4 += 4) {
            int j = cb + c4;
            int gc = ch * NCH + j;
            float4 xo = *(const float4*)(x + (size_t)gr * NC + gc);
            float4 o;
            o.x = 0.5f * (patch[r * T_PS + j + 0] + g_bbig[gc + 0]) + 0.5f * xo.x;
            o.y = 0.5f * (patch[r * T_PS + j + 1] + g_bbig[gc + 1]) + 0.5f * xo.y;
            o.z = 0.5f * (patch[r * T_PS + j + 2] + g_bbig[gc + 2]) + 0.5f * xo.z;
            o.w = 0.5f * (patch[r * T_PS + j + 3] + g_bbig[gc + 3]) + 0.5f * xo.w;
            *(float4*)(out + (size_t)gr * NC + gc) = o;
        }
        __syncthreads();
    }
}

// ---------------- host launch ----------------
extern "C" void kernel_launch(void* const* d_in, const int* in_sizes, int n_in,
                              void* d_out, int out_size) {
    const float* x   = (const float*)d_in[0];
    const float* lng = (const float*)d_in[1];
    const float* lnb = (const float*)d_in[2];
    const float* Wd  = (const float*)d_in[3];
    const float* bd  = (const float*)d_in[4];
    const float* Wg  = (const float*)d_in[5];
    const float* bg  = (const float*)d_in[6];
    const float* dww = (const float*)d_in[7];
    const float* dwb = (const float*)d_in[8];
    const float* W1  = (const float*)d_in[9];
    const float* b1  = (const float*)d_in[10];
    const float* W2  = (const float*)d_in[11];
    const float* b2  = (const float*)d_in[12];
    // d_in[13..16] = Wq,bq,Wk,bk — dead (softmax over one key == 1)
    const float* Wv  = (const float*)d_in[17];
    const float* bv  = (const float*)d_in[18];
    const float* Wo  = (const float*)d_in[19];
    const float* bo  = (const float*)d_in[20];
    const float* Wu  = (const float*)d_in[21];
    const float* bu  = (const float*)d_in[22];
    const float* Wld = (const float*)d_in[23];
    const float* Wlu = (const float*)d_in[24];
    float* out = (float*)d_out;

    static int smem_set = 0;
    if (!smem_set) {
        cudaFuncSetAttribute(k_glu,  cudaFuncAttributeMaxDynamicSharedMemorySize, GLU_SMEM);
        cudaFuncSetAttribute(k_tail, cudaFuncAttributeMaxDynamicSharedMemorySize, TAIL_SMEM);
        smem_set = 1;
    }

    // ---- weight folding ----
    k_T1<<<256, 256>>>(Wu, Wld);
    k_bu1<<<1, 16>>>(bu, Wld);
    k_Wueff<<<1024, 256>>>(Wu, Wlu);
    k_bueff<<<4, 256>>>(bu, Wlu);
    gemm_f32<<<dim3(4, 4), 256>>>(0, W2, Wv, NCH, NCH, NCH);
    gemm_f32<<<dim3(4, 4), 256>>>(1, nullptr, Wo, NCH, NCH, NCH);
    gemm_f32<<<dim3(16, 4), 256>>>(2, nullptr, nullptr, NCH, NC, NCH);
    k_v1<<<1, 256>>>(b2, Wv, bv);
    k_v2<<<1, 256>>>(Wo, bo);
    k_bbig<<<4, 256>>>();
    k_convWcat<<<2048, 256>>>(Wd, dww, Wg);
    k_convW1<<<256, 256>>>(W1);
    k_convWbig<<<1024, 256>>>();

    // ---- main pipeline ----
    k_glu<<<512, 256, GLU_SMEM>>>(x, lng, lnb, bd, dww, bg, dwb);
    k_tail<<<512, 256, TAIL_SMEM>>>(b1, x, out);
}

// round 6
// speedup vs baseline: 1.1287x; 1.0254x over previous
#include <cuda_runtime.h>
#include <cuda_bf16.h>
#include <mma.h>
#include <cstdint>

using namespace nvcuda;

#define NB 32768
#define NC 1024
#define NCH 256
#define NR 16

// ---------------- device scratch ----------------
__device__ __nv_bfloat16 g_h1[(size_t)NB * NCH];    // GLU output
__device__ __nv_bfloat16 g_Wcat[NC * 2 * NCH];      // [Wd*dw_w | Wg] bf16, [1024,512]
__device__ __nv_bfloat16 g_W1b[NCH * NCH];
__device__ __nv_bfloat16 g_Wbig[NCH * NC];
__device__ float g_T1[NCH * NR];
__device__ float g_Wueff[NCH * NC];
__device__ float g_Wf1[NCH * NCH];
__device__ float g_Wf2[NCH * NCH];
__device__ float g_Wbigf[NCH * NC];
__device__ float g_v2[NCH];
__device__ float g_bu1[NR];
__device__ float g_bueff[NC];
__device__ float g_bbig[NC];

// ---------------- cp.async helpers ----------------
__device__ __forceinline__ void cp16(void* s, const void* g) {
    unsigned int sa = (unsigned int)__cvta_generic_to_shared(s);
    asm volatile("cp.async.cg.shared.global [%0], [%1], 16;\n" :: "r"(sa), "l"(g));
}
__device__ __forceinline__ void cp_commit() { asm volatile("cp.async.commit_group;\n" ::: "memory"); }
template<int N>
__device__ __forceinline__ void cp_wait() { asm volatile("cp.async.wait_group %0;\n" :: "n"(N) : "memory"); }

// ---------------- merged precompute kernels ----------------

// blocks 0..255: T1 row i ; block 256: bu1
__global__ void k_fold1(const float* __restrict__ Wu, const float* __restrict__ Wld,
                        const float* __restrict__ bu) {
    int tid = threadIdx.x, wid = tid >> 5, lane = tid & 31;
    if (blockIdx.x == 256) {
        if (tid < NR) {
            float s = 0.f;
            for (int c = 0; c < NC; c++) s += bu[c] * Wld[c * NR + tid];
            g_bu1[tid] = s;
        }
        return;
    }
    int i = blockIdx.x;
    float acc[NR];
    #pragma unroll
    for (int r = 0; r < NR; r++) acc[r] = 0.f;
    for (int c = tid; c < NC; c += 256) {
        float w = Wu[i * NC + c];
        #pragma unroll
        for (int r = 0; r < NR; r++) acc[r] += w * Wld[c * NR + r];
    }
    #pragma unroll
    for (int r = 0; r < NR; r++)
        #pragma unroll
        for (int o = 16; o > 0; o >>= 1) acc[r] += __shfl_xor_sync(0xffffffffu, acc[r], o);
    __shared__ float s[8][NR];
    if (lane == 0)
        #pragma unroll
        for (int r = 0; r < NR; r++) s[wid][r] = acc[r];
    __syncthreads();
    if (tid < NR) {
        float v = 0.f;
        #pragma unroll
        for (int w = 0; w < 8; w++) v += s[w][tid];
        g_T1[i * NR + tid] = v;
    }
}

// blocks 0..1023: Wueff ; blocks 1024..1027: bueff
__global__ void k_fold2(const float* __restrict__ Wu, const float* __restrict__ Wlu,
                        const float* __restrict__ bu) {
    if (blockIdx.x >= 1024) {
        int c = (blockIdx.x - 1024) * 256 + threadIdx.x;
        float s = bu[c];
        #pragma unroll
        for (int r = 0; r < NR; r++) s += g_bu1[r] * Wlu[r * NC + c];
        g_bueff[c] = s;
        return;
    }
    int idx = blockIdx.x * 256 + threadIdx.x;
    int i = idx >> 10, c = idx & 1023;
    float s = Wu[idx];
    #pragma unroll
    for (int r = 0; r < NR; r++) s += g_T1[i * NR + r] * Wlu[r * NC + c];
    g_Wueff[idx] = s;
}

__global__ void gemm_f32(int which, const float* __restrict__ Aext,
                         const float* __restrict__ Bext, int M, int N, int K) {
    const float* A; const float* B; float* C;
    if (which == 0)      { A = Aext;   B = Bext;    C = g_Wf1;  }
    else if (which == 1) { A = g_Wf1;  B = Bext;    C = g_Wf2;  }
    else                 { A = g_Wf2;  B = g_Wueff; C = g_Wbigf;}

    __shared__ float As[64][17];
    __shared__ float Bs[16][64];
    int m0 = blockIdx.y * 64, n0 = blockIdx.x * 64;
    int tid = threadIdx.x;
    int ty = tid >> 4, tx = tid & 15;
    float acc[4][4] = {};
    for (int k0 = 0; k0 < K; k0 += 16) {
        #pragma unroll
        for (int l = 0; l < 4; l++) {
            int idx = tid + l * 256;
            int r = idx >> 4, c = idx & 15;
            As[r][c] = A[(size_t)(m0 + r) * K + k0 + c];
        }
        #pragma unroll
        for (int l = 0; l < 4; l++) {
            int idx = tid + l * 256;
            int r = idx >> 6, c = idx & 63;
            Bs[r][c] = B[(size_t)(k0 + r) * N + n0 + c];
        }
        __syncthreads();
        #pragma unroll
        for (int k = 0; k < 16; k++) {
            float a[4], b[4];
            #pragma unroll
            for (int i = 0; i < 4; i++) a[i] = As[ty * 4 + i][k];
            #pragma unroll
            for (int j = 0; j < 4; j++) b[j] = Bs[k][tx * 4 + j];
            #pragma unroll
            for (int i = 0; i < 4; i++)
                #pragma unroll
                for (int j = 0; j < 4; j++) acc[i][j] += a[i] * b[j];
        }
        __syncthreads();
    }
    #pragma unroll
    for (int i = 0; i < 4; i++)
        #pragma unroll
        for (int j = 0; j < 4; j++)
            C[(size_t)(m0 + ty * 4 + i) * N + n0 + tx * 4 + j] = acc[i][j];
}

// single block: v1 = b2@Wv+bv (smem), then v2 = v1@Wo+bo
__global__ void k_v12(const float* __restrict__ b2, const float* __restrict__ Wv,
                      const float* __restrict__ bv, const float* __restrict__ Wo,
                      const float* __restrict__ bo) {
    __shared__ float sv1[NCH];
    int n = threadIdx.x;
    float s = bv[n];
    for (int k = 0; k < NCH; k++) s += b2[k] * Wv[k * NCH + n];
    sv1[n] = s;
    __syncthreads();
    float t = bo[n];
    for (int k = 0; k < NCH; k++) t += sv1[k] * Wo[k * NCH + n];
    g_v2[n] = t;
}

__global__ void k_bbig() {
    int n = blockIdx.x * 256 + threadIdx.x;
    float s = g_bueff[n];
    for (int k = 0; k < NCH; k++) s += g_v2[k] * g_Wueff[k * NC + n];
    g_bbig[n] = s;
}

__global__ void k_convWcat(const float* __restrict__ Wd, const float* __restrict__ dww,
                           const float* __restrict__ Wg) {
    int idx = blockIdx.x * 256 + threadIdx.x;
    int k = idx >> 9, j = idx & 511;
    float v = (j < NCH) ? Wd[k * NCH + j] * dww[j] : Wg[k * NCH + (j - NCH)];
    g_Wcat[idx] = __float2bfloat16(v);
}

// blocks 0..1023: convWbig ; blocks 1024..1279: convW1
__global__ void k_convWx(const float* __restrict__ W1) {
    if (blockIdx.x >= 1024) {
        int idx = (blockIdx.x - 1024) * 256 + threadIdx.x;
        g_W1b[idx] = __float2bfloat16(W1[idx]);
        return;
    }
    int idx = blockIdx.x * 256 + threadIdx.x;
    g_Wbig[idx] = __float2bfloat16(g_Wbigf[idx]);
}

// ---------------- fused LN + GLU GEMM (3-stage B pipeline) ----------------
#define GLU_SAS 1032           // sA stride (bf16 elems)
#define GLU_SBS 520            // sB stride
#define GLU_PS  520            // f32 patch stride
#define GLU_ASZ (64 * GLU_SAS * 2)          // 132096
#define GLU_BSZ (32 * GLU_SBS * 2)          // 33280
#define GLU_SMEM (GLU_ASZ + 3 * GLU_BSZ)    // 231936

__device__ __forceinline__ void glu_prefB(__nv_bfloat16* sB, int k0, int tid) {
    #pragma unroll
    for (int j = 0; j < 8; j++) {
        int idx = tid + j * 256;
        int row = idx >> 6, c16 = idx & 63;
        cp16(sB + row * GLU_SBS + c16 * 8, g_Wcat + (size_t)(k0 + row) * 512 + c16 * 8);
    }
}

__global__ __launch_bounds__(256, 1)
void k_glu(const float* __restrict__ x, const float* __restrict__ lg,
           const float* __restrict__ lb, const float* __restrict__ bd,
           const float* __restrict__ dww, const float* __restrict__ bg,
           const float* __restrict__ dwb) {
    extern __shared__ char smem[];
    __nv_bfloat16* sA = (__nv_bfloat16*)smem;
    __nv_bfloat16* sB[3] = {
        (__nv_bfloat16*)(smem + GLU_ASZ),
        (__nv_bfloat16*)(smem + GLU_ASZ + GLU_BSZ),
        (__nv_bfloat16*)(smem + GLU_ASZ + 2 * GLU_BSZ)
    };
    float* patch = (float*)smem;   // epilogue reuse (may spill into sB0 — B dead then)

    const int tid = threadIdx.x, wid = tid >> 5, lane = tid & 31;
    const int m0 = blockIdx.x * 64;

    glu_prefB(sB[0], 0, tid);
    cp_commit();

    // ---- LayerNorm: 8 rows per warp -> normalized bf16 in sA ----
    {
        float4 lg4[8], lb4[8];
        #pragma unroll
        for (int i = 0; i < 8; i++) {
            lg4[i] = ((const float4*)lg)[lane + i * 32];
            lb4[i] = ((const float4*)lb)[lane + i * 32];
        }
        #pragma unroll
        for (int rr = 0; rr < 8; rr++) {
            int r = wid * 8 + rr;
            const float4* xr = (const float4*)(x + (size_t)(m0 + r) * NC);
            float4 v[8];
            float s = 0.f, q = 0.f;
            #pragma unroll
            for (int i = 0; i < 8; i++) {
                v[i] = xr[lane + i * 32];
                s += v[i].x + v[i].y + v[i].z + v[i].w;
                q = fmaf(v[i].x, v[i].x, q); q = fmaf(v[i].y, v[i].y, q);
                q = fmaf(v[i].z, v[i].z, q); q = fmaf(v[i].w, v[i].w, q);
            }
            #pragma unroll
            for (int o = 16; o > 0; o >>= 1) {
                s += __shfl_xor_sync(0xffffffffu, s, o);
                q += __shfl_xor_sync(0xffffffffu, q, o);
            }
            float mean = s * (1.f / NC);
            float rstd = rsqrtf(q * (1.f / NC) - mean * mean + 1e-5f);
            #pragma unroll
            for (int i = 0; i < 8; i++) {
                __align__(8) __nv_bfloat16 o4[4];
                o4[0] = __float2bfloat16((v[i].x - mean) * rstd * lg4[i].x + lb4[i].x);
                o4[1] = __float2bfloat16((v[i].y - mean) * rstd * lg4[i].y + lb4[i].y);
                o4[2] = __float2bfloat16((v[i].z - mean) * rstd * lg4[i].z + lb4[i].z);
                o4[3] = __float2bfloat16((v[i].w - mean) * rstd * lg4[i].w + lb4[i].w);
                *(uint2*)(sA + r * GLU_SAS + (lane + i * 32) * 4) = *(const uint2*)o4;
            }
        }
    }
    glu_prefB(sB[1], 32, tid);
    cp_commit();
    cp_wait<1>();        // chunk 0 landed; chunk 1 may still fly
    __syncthreads();

    // ---- main K loop: 32 chunks of K=32, 3-stage pipeline ----
    const int wm = wid >> 2, wn = wid & 3;   // warp tile 32x128 of 64x512
    wmma::fragment<wmma::accumulator, 16, 16, 16, float> acc[2][8];
    #pragma unroll
    for (int i = 0; i < 2; i++)
        #pragma unroll
        for (int j = 0; j < 8; j++) wmma::fill_fragment(acc[i][j], 0.f);

    for (int it = 0; it < 32; it++) {
        int k0 = it * 32;
        if (it + 2 < 32) { glu_prefB(sB[(it + 2) % 3], k0 + 64, tid); cp_commit(); }
        __nv_bfloat16* sBc = sB[it % 3];
        #pragma unroll
        for (int kk = 0; kk < 32; kk += 16) {
            wmma::fragment<wmma::matrix_a, 16, 16, 16, __nv_bfloat16, wmma::row_major> af[2];
            wmma::fragment<wmma::matrix_b, 16, 16, 16, __nv_bfloat16, wmma::row_major> bf[8];
            #pragma unroll
            for (int i = 0; i < 2; i++)
                wmma::load_matrix_sync(af[i], sA + (wm * 32 + i * 16) * GLU_SAS + k0 + kk, GLU_SAS);
            #pragma unroll
            for (int j = 0; j < 8; j++)
                wmma::load_matrix_sync(bf[j], sBc + kk * GLU_SBS + wn * 128 + j * 16, GLU_SBS);
            #pragma unroll
            for (int i = 0; i < 2; i++)
                #pragma unroll
                for (int j = 0; j < 8; j++)
                    wmma::mma_sync(acc[i][j], af[i], bf[j], acc[i][j]);
        }
        if (it < 31) {
            if (it < 30) cp_wait<1>();   // next chunk landed; newest may fly
            else         cp_wait<0>();   // it==30: drain last chunk (31)
            __syncthreads();
        }
    }
    __syncthreads();

    // ---- epilogue: GLU combine -> g_h1 ----
    #pragma unroll
    for (int i = 0; i < 2; i++)
        #pragma unroll
        for (int j = 0; j < 8; j++)
            wmma::store_matrix_sync(patch + (size_t)(wm * 32 + i * 16) * GLU_PS + wn * 128 + j * 16,
                                    acc[i][j], GLU_PS, wmma::mem_row_major);
    __syncthreads();

    const int r = tid >> 2;
    const int cb = (tid & 3) * 64;
    #pragma unroll
    for (int c8 = 0; c8 < 64; c8 += 8) {
        __align__(16) __nv_bfloat16 tmp[8];
        #pragma unroll
        for (int t = 0; t < 8; t++) {
            int j = cb + c8 + t;
            float a = patch[r * GLU_PS + j] + bd[j] * dww[j];
            float g = patch[r * GLU_PS + 256 + j] + bg[j];
            float sg = 1.f / (1.f + expf(-g));
            tmp[t] = __float2bfloat16(a * sg + dwb[j]);
        }
        *(uint4*)(g_h1 + (size_t)(m0 + r) * NCH + cb + c8) = *(const uint4*)tmp;
    }
}

// ---------------- fused tail (unchanged from R4 passing version) ----------------
#define T_S  264
#define T_PS 260
#define T_OFF_A1 0
#define T_OFF_W1 33792
#define T_OFF_PATCH 33792
#define T_OFF_WB0 101376
#define T_OFF_WB1 135168
#define T_OFF_U 168960
#define TAIL_SMEM 202752

__device__ __forceinline__ float gelu_tanh(float v) {
    return 0.5f * v * (1.f + tanhf(0.7978845608028654f * (v + 0.044715f * v * v * v)));
}

__device__ __forceinline__ void tail_prefWb(char* smem, int buf, int ch, int k0, int tid) {
    __nv_bfloat16* dst = (__nv_bfloat16*)(smem + (buf ? T_OFF_WB1 : T_OFF_WB0));
    #pragma unroll
    for (int j = 0; j < 8; j++) {
        int idx = tid + j * 256;
        int row = idx >> 5, c16 = idx & 31;
        cp16(dst + row * T_S + c16 * 8, g_Wbig + (size_t)(k0 + row) * NC + ch * NCH + c16 * 8);
    }
}

__global__ __launch_bounds__(256, 1)
void k_tail(const float* __restrict__ b1, const float* __restrict__ x,
            float* __restrict__ out) {
    extern __shared__ char smem[];
    __nv_bfloat16* sA1 = (__nv_bfloat16*)(smem + T_OFF_A1);
    __nv_bfloat16* sW1 = (__nv_bfloat16*)(smem + T_OFF_W1);
    __nv_bfloat16* sU  = (__nv_bfloat16*)(smem + T_OFF_U);
    float* patch = (float*)(smem + T_OFF_PATCH);

    const int tid = threadIdx.x, wid = tid >> 5;
    const int wm = wid >> 2, wn = wid & 3;
    const int m0 = blockIdx.x * 64;

    #pragma unroll
    for (int j = 0; j < 8; j++) {
        int idx = tid + j * 256;
        int row = idx >> 5, c16 = idx & 31;
        cp16(sA1 + row * T_S + c16 * 8, g_h1 + (size_t)(m0 + row) * NCH + c16 * 8);
    }
    #pragma unroll
    for (int j = 0; j < 32; j++) {
        int idx = tid + j * 256;
        int row = idx >> 5, c16 = idx & 31;
        cp16(sW1 + row * T_S + c16 * 8, g_W1b + (size_t)row * NCH + c16 * 8);
    }
    cp_commit();
    cp_wait<0>();
    __syncthreads();

    {
        wmma::fragment<wmma::accumulator, 16, 16, 16, float> acc1[2][4];
        #pragma unroll
        for (int i = 0; i < 2; i++)
            #pragma unroll
            for (int j = 0; j < 4; j++) wmma::fill_fragment(acc1[i][j], 0.f);
        #pragma unroll
        for (int kk = 0; kk < NCH; kk += 16) {
            wmma::fragment<wmma::matrix_a, 16, 16, 16, __nv_bfloat16, wmma::row_major> af[2];
            wmma::fragment<wmma::matrix_b, 16, 16, 16, __nv_bfloat16, wmma::row_major> bf[4];
            #pragma unroll
            for (int i = 0; i < 2; i++)
                wmma::load_matrix_sync(af[i], sA1 + (wm * 32 + i * 16) * T_S + kk, T_S);
            #pragma unroll
            for (int j = 0; j < 4; j++)
                wmma::load_matrix_sync(bf[j], sW1 + kk * T_S + wn * 64 + j * 16, T_S);
            #pragma unroll
            for (int i = 0; i < 2; i++)
                #pragma unroll
                for (int j = 0; j < 4; j++)
                    wmma::mma_sync(acc1[i][j], af[i], bf[j], acc1[i][j]);
        }
        __syncthreads();   // all reads of sW1 done before WB0 prefetch / patch overwrite

        tail_prefWb(smem, 0, 0, 0, tid);
        cp_commit();

        #pragma unroll
        for (int i = 0; i < 2; i++)
            #pragma unroll
            for (int j = 0; j < 4; j++)
                wmma::store_matrix_sync(patch + (size_t)(wm * 32 + i * 16) * T_PS + wn * 64 + j * 16,
                                        acc1[i][j], T_PS, wmma::mem_row_major);
        __syncthreads();
        const int r = tid >> 2, cb = (tid & 3) * 64;
        #pragma unroll
        for (int c8 = 0; c8 < 64; c8 += 8) {
            __align__(16) __nv_bfloat16 tmp[8];
            #pragma unroll
            for (int t = 0; t < 8; t++) {
                int j = cb + c8 + t;
                tmp[t] = __float2bfloat16(gelu_tanh(patch[r * T_PS + j] + b1[j]));
            }
            *(uint4*)(sU + r * T_S + cb + c8) = *(const uint4*)tmp;
        }
        __syncthreads();
    }

    for (int ch = 0; ch < 4; ch++) {
        wmma::fragment<wmma::accumulator, 16, 16, 16, float> acc2[2][4];
        #pragma unroll
        for (int i = 0; i < 2; i++)
            #pragma unroll
            for (int j = 0; j < 4; j++) wmma::fill_fragment(acc2[i][j], 0.f);

        for (int k0 = 0; k0 < NCH; k0 += 64) {
            int t = ch * 4 + (k0 >> 6);
            int cur = t & 1;
            cp_wait<0>();
            __syncthreads();
            if (k0 + 64 < NCH)       tail_prefWb(smem, cur ^ 1, ch, k0 + 64, tid);
            else if (ch + 1 < 4)     tail_prefWb(smem, cur ^ 1, ch + 1, 0, tid);
            if (t < 15) cp_commit();
            __nv_bfloat16* sWb = (__nv_bfloat16*)(smem + (cur ? T_OFF_WB1 : T_OFF_WB0));
            #pragma unroll
            for (int kk = 0; kk < 64; kk += 16) {
                wmma::fragment<wmma::matrix_a, 16, 16, 16, __nv_bfloat16, wmma::row_major> af[2];
                wmma::fragment<wmma::matrix_b, 16, 16, 16, __nv_bfloat16, wmma::row_major> bf[4];
                #pragma unroll
                for (int i = 0; i < 2; i++)
                    wmma::load_matrix_sync(af[i], sU + (wm * 32 + i * 16) * T_S + k0 + kk, T_S);
                #pragma unroll
                for (int j = 0; j < 4; j++)
                    wmma::load_matrix_sync(bf[j], sWb + kk * T_S + wn * 64 + j * 16, T_S);
                #pragma unroll
                for (int i = 0; i < 2; i++)
                    #pragma unroll
                    for (int j = 0; j < 4; j++)
                        wmma::mma_sync(acc2[i][j], af[i], bf[j], acc2[i][j]);
            }
            __syncthreads();
        }

        #pragma unroll
        for (int i = 0; i < 2; i++)
            #pragma unroll
            for (int j = 0; j < 4; j++)
                wmma::store_matrix_sync(patch + (size_t)(wm * 32 + i * 16) * T_PS + wn * 64 + j * 16,
                                        acc2[i][j], T_PS, wmma::mem_row_major);
        __syncthreads();
        const int r = tid >> 2, cb = (tid & 3) * 64;
        const int gr = m0 + r;
        #pragma unroll
        for (int c4 = 0; c4 < 64; c4 += 4) {
            int j = cb + c4;
            int gc = ch * NCH + j;
            float4 xo = *(const float4*)(x + (size_t)gr * NC + gc);
            float4 o;
            o.x = 0.5f * (patch[r * T_PS + j + 0] + g_bbig[gc + 0]) + 0.5f * xo.x;
            o.y = 0.5f * (patch[r * T_PS + j + 1] + g_bbig[gc + 1]) + 0.5f * xo.y;
            o.z = 0.5f * (patch[r * T_PS + j + 2] + g_bbig[gc + 2]) + 0.5f * xo.z;
            o.w = 0.5f * (patch[r * T_PS + j + 3] + g_bbig[gc + 3]) + 0.5f * xo.w;
            *(float4*)(out + (size_t)gr * NC + gc) = o;
        }
        __syncthreads();
    }
}

// ---------------- host launch ----------------
extern "C" void kernel_launch(void* const* d_in, const int* in_sizes, int n_in,
                              void* d_out, int out_size) {
    const float* x   = (const float*)d_in[0];
    const float* lng = (const float*)d_in[1];
    const float* lnb = (const float*)d_in[2];
    const float* Wd  = (const float*)d_in[3];
    const float* bd  = (const float*)d_in[4];
    const float* Wg  = (const float*)d_in[5];
    const float* bg  = (const float*)d_in[6];
    const float* dww = (const float*)d_in[7];
    const float* dwb = (const float*)d_in[8];
    const float* W1  = (const float*)d_in[9];
    const float* b1  = (const float*)d_in[10];
    const float* W2  = (const float*)d_in[11];
    const float* b2  = (const float*)d_in[12];
    // d_in[13..16] = Wq,bq,Wk,bk — dead (softmax over one key == 1)
    const float* Wv  = (const float*)d_in[17];
    const float* bv  = (const float*)d_in[18];
    const float* Wo  = (const float*)d_in[19];
    const float* bo  = (const float*)d_in[20];
    const float* Wu  = (const float*)d_in[21];
    const float* bu  = (const float*)d_in[22];
    const float* Wld = (const float*)d_in[23];
    const float* Wlu = (const float*)d_in[24];
    float* out = (float*)d_out;

    static int smem_set = 0;
    if (!smem_set) {
        cudaFuncSetAttribute(k_glu,  cudaFuncAttributeMaxDynamicSharedMemorySize, GLU_SMEM);
        cudaFuncSetAttribute(k_tail, cudaFuncAttributeMaxDynamicSharedMemorySize, TAIL_SMEM);
        smem_set = 1;
    }

    k_convWcat<<<2048, 256>>>(Wd, dww, Wg);                         // 0
    k_fold1<<<257, 256>>>(Wu, Wld, bu);                             // 1
    k_fold2<<<1028, 256>>>(Wu, Wlu, bu);                            // 2
    k_glu<<<512, 256, GLU_SMEM>>>(x, lng, lnb, bd, dww, bg, dwb);   // 3  <- profiled slot
    gemm_f32<<<dim3(4, 4), 256>>>(0, W2, Wv, NCH, NCH, NCH);        // 4
    gemm_f32<<<dim3(4, 4), 256>>>(1, nullptr, Wo, NCH, NCH, NCH);   // 5
    k_v12<<<1, 256>>>(b2, Wv, bv, Wo, bo);                          // 6
    gemm_f32<<<dim3(16, 4), 256>>>(2, nullptr, nullptr, NCH, NC, NCH); // 7
    k_bbig<<<4, 256>>>();                                           // 8
    k_convWx<<<1280, 256>>>(W1);                                    // 9
    k_tail<<<512, 256, TAIL_SMEM>>>(b1, x, out);                    // 10
}